// round 11
// baseline (speedup 1.0000x reference)
#include <cuda_runtime.h>
#include <math.h>
#include <stdint.h>

#define TT 2048
#define BB 64
#define DD 256
#define HH 512
#define NGROUPS 8
#define GC 16
#define GB 8
#define JC 32
#define NT 256

#define FMA_X2(d, a, b, c) \
    asm("fma.rn.f32x2 %0, %1, %2, %3;" : "=l"(d) : "l"(a), "l"(b), "l"(c))
#define ADD_X2(d, a, b) \
    asm("add.rn.f32x2 %0, %1, %2;" : "=l"(d) : "l"(a), "l"(b))
#define DUP_X2(d, s) \
    asm("mov.b64 %0, {%1, %1};" : "=l"(d) : "r"(__float_as_uint(s)))
#define UNPACK_X2(lo, hi, p) \
    asm("mov.b64 {%0, %1}, %2;" : "=r"(lo), "=r"(hi) : "l"(p))
#define PACK_X2(d, lo, hi) \
    asm("mov.b64 %0, {%1, %2};" : "=l"(d) : "f"(lo), "f"(hi))

// ---- cluster primitives ----
#define MBAR_INIT(addr, cnt) \
    asm volatile("mbarrier.init.shared.b64 [%0], %1;" :: "r"(addr), "r"(cnt) : "memory")
#define ST_CLUSTER_U64(addr, c, val) \
    asm volatile("{.reg .u32 rr; mapa.shared::cluster.u32 rr, %0, %1;\n\t" \
                 "st.shared::cluster.u64 [rr], %2;}" :: "r"(addr), "r"(c), "l"(val) : "memory")
#define MBAR_ARRIVE_REMOTE(addr, c) \
    asm volatile("{.reg .u32 rr; mapa.shared::cluster.u32 rr, %0, %1;\n\t" \
                 "mbarrier.arrive.release.cluster.shared::cluster.b64 _, [rr];}" \
                 :: "r"(addr), "r"(c) : "memory")
#define FENCE_CLU() asm volatile("fence.acq_rel.cluster;" ::: "memory")
#define MBAR_WAIT(addr, parity) do { \
    uint32_t _d; \
    asm volatile("{.reg .pred p; mbarrier.try_wait.parity.acquire.cluster.shared::cta.b64 p, [%1], %2;\n\t" \
                 "selp.b32 %0, 1, 0, p;}" : "=r"(_d) : "r"(addr), "r"(parity) : "memory"); \
    if (!_d) { \
        asm volatile("{.reg .pred P1;\n\t" \
                     "WL_%=: mbarrier.try_wait.parity.acquire.cluster.shared::cta.b64 P1, [%0], %1, 0x989680;\n\t" \
                     "@P1 bra.uni WD_%=;\n\t bra.uni WL_%=;\n\t WD_%=:}" \
                     :: "r"(addr), "r"(parity) : "memory"); \
    } } while (0)

__device__ __forceinline__ uint32_t smem_u32(const void* p) {
    uint32_t a;
    asm("{ .reg .u64 t; cvta.to.shared.u64 t, %1; cvt.u32.u64 %0, t; }" : "=r"(a) : "l"(p));
    return a;
}

__device__ float g_Gx[(size_t)TT * 3 * BB * HH];

// =====================================================================================
// Phase 1 (R5-proven, unchanged)
// =====================================================================================
__global__ void __launch_bounds__(256) phase1_gemm(
    const float* __restrict__ x,
    const float* __restrict__ Wz, const float* __restrict__ bz,
    const float* __restrict__ Wr, const float* __restrict__ br,
    const float* __restrict__ Wh, const float* __restrict__ bh)
{
    __shared__ float xs[32 * 132];
    __shared__ float ws[32 * 64];

    const int gate = blockIdx.y >> 3;
    const int jt0  = (blockIdx.y & 7) * 64;
    const float* W    = (gate == 0) ? Wz : ((gate == 1) ? Wr : Wh);
    const float* bias = (gate == 0) ? bz : ((gate == 1) ? br : bh);
    const int m0  = blockIdx.x * 128;
    const int tid = threadIdx.x;
    const int tn = tid & 15;
    const int tm = tid >> 4;

    unsigned long long pa[4][4];
#pragma unroll
    for (int i = 0; i < 4; i++)
#pragma unroll
        for (int j = 0; j < 4; j++) pa[i][j] = 0ull;

    for (int kc = 0; kc < 8; kc++) {
#pragma unroll
        for (int i = 0; i < 16; i++) {
            int idx = tid + i * 256;
            int row = idx >> 5, kk = idx & 31;
            xs[kk * 132 + row] = x[(size_t)(m0 + row) * DD + kc * 32 + kk];
        }
#pragma unroll
        for (int i = 0; i < 8; i++) {
            int idx = tid + i * 256;
            int kk = idx >> 6, jj = idx & 63;
            ws[kk * 64 + jj] = W[(size_t)(kc * 32 + kk) * HH + jt0 + jj];
        }
        __syncthreads();
#pragma unroll 8
        for (int kk = 0; kk < 32; kk++) {
            float4 w4 = *(const float4*)&ws[kk * 64 + tn * 4];
            ulonglong2 xL = *(const ulonglong2*)&xs[kk * 132 + tm * 8];
            ulonglong2 xH = *(const ulonglong2*)&xs[kk * 132 + tm * 8 + 4];
            unsigned long long hp[4] = {xL.x, xL.y, xH.x, xH.y};
            unsigned long long wd[4];
            DUP_X2(wd[0], w4.x); DUP_X2(wd[1], w4.y);
            DUP_X2(wd[2], w4.z); DUP_X2(wd[3], w4.w);
#pragma unroll
            for (int i = 0; i < 4; i++)
#pragma unroll
                for (int j = 0; j < 4; j++)
                    FMA_X2(pa[i][j], hp[i], wd[j], pa[i][j]);
        }
        __syncthreads();
    }

#pragma unroll
    for (int i = 0; i < 4; i++) {
#pragma unroll
        for (int j = 0; j < 4; j++) {
            unsigned lo, hi;
            UNPACK_X2(lo, hi, pa[i][j]);
            float bj = bias[jt0 + tn * 4 + j];
            int mA = m0 + tm * 8 + 2 * i;
            int tA = mA >> 6, bA = mA & 63;
            g_Gx[(((size_t)tA * 3 + gate) * BB + bA) * HH + jt0 + tn * 4 + j] =
                __uint_as_float(lo) + bj;
            int mB = mA + 1;
            int tB = mB >> 6, bB = mB & 63;
            g_Gx[(((size_t)tB * 3 + gate) * BB + bB) * HH + jt0 + tn * 4 + j] =
                __uint_as_float(hi) + bj;
        }
    }
}

// =====================================================================================
// Phase 2: cluster DSMEM GRU. SMEM byte offsets.
// =====================================================================================
#define OFF_HLO 196608    // h pairs (b0,b1),(b2,b3): [512] rows x 16B
#define OFF_HHI 204800    // h pairs (b4..b7)
#define OFF_RLO 212992    // rh pairs lo
#define OFF_RHI 221184    // rh pairs hi
#define OFF_PART 229376   // [4][32] u64 stage-2 partials
#define OFF_MBR 230400
#define OFF_MBH 230408
#define SMEM_P2 230416

template<int KI>
__device__ __forceinline__ void dotK(const float* wbase, const char* lo, const char* hi,
                                     int slotA, int slotB, unsigned long long* a2)
{
    const float4* wp = (const float4*)wbase;
#pragma unroll
    for (int i = 0; i < KI; i++) {
        float4 w0 = wp[slotA], w1 = wp[slotB];
        ulonglong2 hL = *(const ulonglong2*)lo;
        ulonglong2 hH = *(const ulonglong2*)hi;
        unsigned long long hb[4] = {hL.x, hL.y, hH.x, hH.y};
        unsigned long long wd[8];
        DUP_X2(wd[0], w0.x); DUP_X2(wd[1], w0.y);
        DUP_X2(wd[2], w0.z); DUP_X2(wd[3], w0.w);
        DUP_X2(wd[4], w1.x); DUP_X2(wd[5], w1.y);
        DUP_X2(wd[6], w1.z); DUP_X2(wd[7], w1.w);
#pragma unroll
        for (int p = 0; p < 4; p++)
#pragma unroll
            for (int j = 0; j < 8; j++)
                FMA_X2(a2[p * 8 + j], hb[p], wd[j], a2[p * 8 + j]);
        wp += 32 * JC / 4;
        lo += 32 * 16;
        hi += 32 * 16;
    }
}

__device__ __forceinline__ void bfly(unsigned long long* a2, int lane)
{
#pragma unroll
    for (int s = 0; s < 5; s++) {
        const int m = 16 >> s, half = 16 >> s;
        bool up = (lane & m) != 0;
#pragma unroll
        for (int i = 0; i < half; i++) {
            unsigned long long send = up ? a2[i] : a2[i + half];
            unsigned long long r = __shfl_xor_sync(0xffffffffu, send, m);
            unsigned long long keep = up ? a2[i + half] : a2[i];
            ADD_X2(a2[i], keep, r);
        }
    }
}

__global__ void __launch_bounds__(NT, 1) phase2_gru(
    const float* __restrict__ h0in,
    const float* __restrict__ Wz,
    const float* __restrict__ Wr,
    const float* __restrict__ Wh,
    float* __restrict__ out)
{
    extern __shared__ char smc[];
    float* wzs = (float*)smc;
    float* wrs = wzs + HH * JC;
    float* whs = wrs + HH * JC;
    unsigned long long* partU = (unsigned long long*)(smc + OFF_PART);

    const uint32_t baseU = smem_u32(smc);
    const uint32_t mbR = baseU + OFF_MBR, mbH = baseU + OFF_MBH;
    uint32_t rank;
    asm("mov.u32 %0, %%cluster_ctarank;" : "=r"(rank));
    const int b0 = (blockIdx.x >> 4) * GB;
    const int j0 = (int)rank * JC;
    const int tid  = threadIdx.x;
    const int warp = tid >> 5;
    const int lane = tid & 31;

    if (tid == 0) { MBAR_INIT(mbR, GC); MBAR_INIT(mbH, GC); }

    for (int idx = tid; idx < HH * JC; idx += NT) {
        int k = idx >> 5, jl = idx & 31;
        int phys = k * JC + ((((jl >> 2) ^ (k & 7))) << 2) + (jl & 3);
        size_t goff = (size_t)(DD + k) * HH + j0 + jl;
        wzs[phys] = Wz[goff];
        wrs[phys] = Wr[goff];
        whs[phys] = Wh[goff];
    }
    // t=0: local fill of h pair-buffers from h0
#pragma unroll
    for (int q = 0; q < 2; q++) {
        int k = tid + q * NT;
#pragma unroll
        for (int b2 = 0; b2 < 4; b2++) {
            float vlo = h0in[(size_t)(b0 + 2 * b2) * HH + k];
            float vhi = h0in[(size_t)(b0 + 2 * b2 + 1) * HH + k];
            unsigned long long v;
            PACK_X2(v, vlo, vhi);
            *(unsigned long long*)(smc + ((b2 < 2) ? OFF_HLO : OFF_HHI) + k * 16 + (b2 & 1) * 8) = v;
        }
    }
    __syncthreads();
    asm volatile("barrier.cluster.arrive.aligned;" ::: "memory");
    asm volatile("barrier.cluster.wait.aligned;" ::: "memory");

    const int gateR = warp >> 2;                 // 0 = z-warps (+stage2 k-lo), 1 = r (+k-hi)
    const int jt    = warp & 3;
    const int slotA = (jt * 2) ^ (lane & 7);
    const int slotB = (jt * 2 + 1) ^ (lane & 7);
    const int bp    = lane >> 3;
    const int jl_o  = jt * 8 + (lane & 7);
    const uint32_t pairOff = (uint32_t)(j0 + jl_o) * 16 + (uint32_t)(bp & 1) * 8;
    const uint32_t offH = ((bp < 2) ? OFF_HLO : OFF_HHI) + pairOff;
    const uint32_t offR = ((bp < 2) ? OFF_RLO : OFF_RHI) + pairOff;
    const uint32_t myHAddr = baseU + offH;
    const uint32_t myRAddr = baseU + offR;
    const int bA = 2 * bp, bB = 2 * bp + 1;

    for (int t = 0; t < TT; t++) {
        const uint32_t pt = (uint32_t)(t & 1);

        // Gx prefetch (own stage-1 gate; gate2 on warps 0-3)
        size_t rg = (((size_t)t * 3 + gateR) * BB + b0 + bA) * HH + j0 + jl_o;
        float gxA0 = __ldg(&g_Gx[rg]), gxA1 = __ldg(&g_Gx[rg + HH]);
        float gx20 = 0.f, gx21 = 0.f;
        if (gateR == 0) {
            size_t r2 = (((size_t)t * 3 + 2) * BB + b0 + bA) * HH + j0 + jl_o;
            gx20 = __ldg(&g_Gx[r2]);
            gx21 = __ldg(&g_Gx[r2 + HH]);
        }
        // h_old pair (own column) -> registers
        float ho0, ho1;
        {
            unsigned long long hv = *(const unsigned long long*)(smc + offH);
            unsigned l_, h_;
            UNPACK_X2(l_, h_, hv);
            ho0 = __uint_as_float(l_);
            ho1 = __uint_as_float(h_);
        }

        // ---------- stage 1: full-K dot (z on warps 0-3, r on warps 4-7) ----------
        unsigned long long a2[32];
#pragma unroll
        for (int v = 0; v < 32; v++) a2[v] = 0ull;
        dotK<16>((gateR ? wrs : wzs) + lane * JC,
                 smc + OFF_HLO + lane * 16, smc + OFF_HHI + lane * 16, slotA, slotB, a2);
        bfly(a2, lane);

        float z0 = 0.f, z1 = 0.f;
        {
            unsigned lo, hi;
            UNPACK_X2(lo, hi, a2[0]);
            float s0 = 1.f / (1.f + __expf(-(__uint_as_float(lo) + gxA0)));
            float s1 = 1.f / (1.f + __expf(-(__uint_as_float(hi) + gxA1)));
            if (gateR == 0) {
                z0 = s0; z1 = s1;               // stays in registers
            } else {
                unsigned long long v;
                PACK_X2(v, s0 * ho0, s1 * ho1);
#pragma unroll
                for (int c = 0; c < GC; c++)
                    ST_CLUSTER_U64(myRAddr, (rank + c) & 15, v);
            }
        }
        __syncthreads();
        if (tid < GC) { FENCE_CLU(); MBAR_ARRIVE_REMOTE(mbR, ((int)rank + tid) & 15); }
        MBAR_WAIT(mbR, pt);

        // ---------- stage 2: half-K candidate dot ----------
#pragma unroll
        for (int v = 0; v < 32; v++) a2[v] = 0ull;
        {
            const int k0 = gateR * 256 + lane;
            dotK<8>(whs + k0 * JC, smc + OFF_RLO + k0 * 16, smc + OFF_RHI + k0 * 16,
                    slotA, slotB, a2);
        }
        bfly(a2, lane);
        if (gateR == 1) partU[jt * 32 + lane] = a2[0];
        __syncthreads();
        if (gateR == 0) {
            unsigned long long tot;
            ADD_X2(tot, a2[0], partU[jt * 32 + lane]);
            unsigned lo, hi;
            UNPACK_X2(lo, hi, tot);
            float ht0 = tanhf(__uint_as_float(lo) + gx20);
            float ht1 = tanhf(__uint_as_float(hi) + gx21);
            float hn0 = ho0 + z0 * (ht0 - ho0);
            float hn1 = ho1 + z1 * (ht1 - ho1);
            out[((size_t)t * BB + b0 + bA) * HH + j0 + jl_o] = hn0;
            out[((size_t)t * BB + b0 + bB) * HH + j0 + jl_o] = hn1;
            unsigned long long v;
            PACK_X2(v, hn0, hn1);
#pragma unroll
            for (int c = 0; c < GC; c++)
                ST_CLUSTER_U64(myHAddr, (rank + c) & 15, v);
        }
        __syncthreads();
        if (tid < GC) { FENCE_CLU(); MBAR_ARRIVE_REMOTE(mbH, ((int)rank + tid) & 15); }
        MBAR_WAIT(mbH, pt);
    }
}

// =====================================================================================
extern "C" void kernel_launch(void* const* d_in, const int* in_sizes, int n_in,
                              void* d_out, int out_size)
{
    const float* x  = (const float*)d_in[0];
    const float* h0 = (const float*)d_in[1];
    const float* Wz = (const float*)d_in[2];
    const float* bz = (const float*)d_in[3];
    const float* Wr = (const float*)d_in[4];
    const float* br = (const float*)d_in[5];
    const float* Wh = (const float*)d_in[6];
    const float* bh = (const float*)d_in[7];
    float* out = (float*)d_out;

    cudaFuncSetAttribute(phase2_gru, cudaFuncAttributeMaxDynamicSharedMemorySize, SMEM_P2);
    cudaFuncSetAttribute(phase2_gru, cudaFuncAttributeNonPortableClusterSizeAllowed, 1);

    dim3 g1((TT * BB) / 128, 24);
    phase1_gemm<<<g1, 256>>>(x, Wz, bz, Wr, br, Wh, bh);

    cudaLaunchConfig_t cfg = {};
    cfg.gridDim = dim3(NGROUPS * GC, 1, 1);
    cfg.blockDim = dim3(NT, 1, 1);
    cfg.dynamicSmemBytes = SMEM_P2;
    cfg.stream = 0;
    cudaLaunchAttribute attrs[1];
    attrs[0].id = cudaLaunchAttributeClusterDimension;
    attrs[0].val.clusterDim.x = GC;
    attrs[0].val.clusterDim.y = 1;
    attrs[0].val.clusterDim.z = 1;
    cfg.attrs = attrs;
    cfg.numAttrs = 1;
    cudaLaunchKernelEx(&cfg, phase2_gru, h0, Wz, Wr, Wh, out);
}